// round 9
// baseline (speedup 1.0000x reference)
#include <cuda_runtime.h>
#include <math.h>

#define NIMG 256
#define EMB  1600
#define HIDD 400
#define KNBR 11   // self + 10 neighbors

// ---------------- scratch (__device__ globals; no allocs allowed) ----------------
__device__ float g_conv[(size_t)NIMG*64*84*84];   // conv output tmp (reused per block)
__device__ float g_bufA[(size_t)NIMG*64*42*42];   // pooled ping
__device__ float g_bufB[(size_t)NIMG*64*21*21];   // pooled pong (final z lives here)
__device__ float g_wt[4*36864];                   // transposed weights, per layer: [ic][tap][oc]
__device__ float g_part[(size_t)14336*128];       // per-CTA partial sums (64 sum + 64 sumsq)
__device__ float g_scale[64];
__device__ float g_shift[64];
__device__ float g_zn[NIMG*EMB];
__device__ float g_znT[EMB*NIMG];
__device__ float g_sim[NIMG*NIMG];
__device__ int   g_nbr[NIMG*KNBR];
__device__ float g_xl1[NIMG*HIDD];
__device__ float g_xr1[NIMG*HIDD];
__device__ float g_h1 [NIMG*HIDD];
__device__ float g_xl2[(size_t)NIMG*4*EMB];
__device__ float g_xr2[(size_t)NIMG*4*EMB];

// ---------------- packed f32x2 helpers (Blackwell; ptxas never auto-fuses) -------
__device__ __forceinline__ unsigned long long pack2(float lo, float hi) {
    unsigned long long p;
    asm("mov.b64 %0, {%1, %2};" : "=l"(p) : "r"(__float_as_uint(lo)), "r"(__float_as_uint(hi)));
    return p;
}
__device__ __forceinline__ void unpack2(unsigned long long p, float& lo, float& hi) {
    unsigned a, b;
    asm("mov.b64 {%0, %1}, %2;" : "=r"(a), "=r"(b) : "l"(p));
    lo = __uint_as_float(a); hi = __uint_as_float(b);
}
__device__ __forceinline__ unsigned long long fma2(unsigned long long a, unsigned long long b,
                                                   unsigned long long c) {
    unsigned long long d;
    asm("fma.rn.f32x2 %0, %1, %2, %3;" : "=l"(d) : "l"(a), "l"(b), "l"(c));
    return d;
}

// ---------------- dummy (profiler slot alignment; overwritten before use) --------
__global__ void dummy_kernel() {
    if (threadIdx.x < 64) g_scale[threadIdx.x] = 0.f;
}

// ---------------- weight transpose: all 4 layers, OIHW -> [ic][tap][oc] ----------------
__global__ void prep_all_kernel(const float* __restrict__ w1, const float* __restrict__ w2,
                                const float* __restrict__ w3, const float* __restrict__ w4) {
    int i = blockIdx.x*256 + threadIdx.x;
    if (i < 1728) {                       // layer 0: CIN=3
        int oc = i / 27, rest = i % 27;
        int ic = rest / 9, t = rest % 9;
        g_wt[ic*576 + t*64 + oc] = w1[i];
    } else {
        int j = i - 1728;
        int l = j / 36864 + 1;
        if (l <= 3) {
            int k = j % 36864;
            int oc = k / 576, rest = k % 576;
            int ic = rest / 9, t = rest % 9;
            const float* w = (l == 1) ? w2 : (l == 2) ? w3 : w4;
            g_wt[l*36864 + ic*576 + t*64 + oc] = w[k];
        }
    }
}

// ---------------- 3x3 SAME conv + bias + fused per-CTA BN partial stats ----------------
// 256 threads: two oc-groups of 128 threads; each thread = 1 pixel x 32 oc (16 f32x2 pairs).
// All geometry compile-time.
template<int CIN, int CTW, int CTH, int H, int W, int TILESX>
__global__ __launch_bounds__(256) void conv3x3_kernel(
        const float* __restrict__ in, const float* __restrict__ wt,
        const float* __restrict__ bias,
        float* __restrict__ out, float* __restrict__ part) {
    constexpr int ICC = (CIN == 3) ? 3 : 8;       // input-channel chunk in smem
    constexpr int SIN = (CTH+2)*(CTW+2);

    __shared__ float s_in[ICC*SIN];
    __shared__ __align__(16) float s_w[ICC*576];
    __shared__ float s_bias[64];
    __shared__ float s_sum[8][64];
    __shared__ float s_ssq[8][64];

    int n    = blockIdx.y;
    int tile = blockIdx.x;
    int ty0  = (tile / TILESX) * CTH;
    int tx0  = (tile % TILESX) * CTW;
    int tid  = threadIdx.x;
    int og   = tid >> 7;                          // oc group: 0 -> oc 0-31, 1 -> oc 32-63
    int pt   = tid & 127;                         // pixel slot within tile
    bool active = (pt < CTW*CTH);
    int r = active ? (pt / CTW) : 0;
    int c = active ? (pt % CTW) : 0;
    int oy = ty0 + r, ox = tx0 + c;
    bool valid = active && (oy < H) && (ox < W);

    if (tid < 64) s_bias[tid] = bias[tid];

    unsigned long long accp[16];
#pragma unroll
    for (int i = 0; i < 16; i++) accp[i] = 0ull;

    const float* inN = in + (size_t)n * CIN * H * W;
    for (int ic0 = 0; ic0 < CIN; ic0 += ICC) {
        for (int i = tid; i < ICC*SIN; i += 256) {
            int icc = i / SIN;
            int p   = i % SIN;
            int ly = p / (CTW+2), lx = p % (CTW+2);
            int gy = ty0 + ly - 1, gx = tx0 + lx - 1;
            float v = 0.f;
            if (gy >= 0 && gy < H && gx >= 0 && gx < W)
                v = inN[(size_t)(ic0+icc)*H*W + gy*W + gx];
            s_in[i] = v;
        }
        for (int i = tid; i < ICC*576; i += 256) s_w[i] = wt[ic0*576 + i];
        __syncthreads();
#pragma unroll
        for (int icc = 0; icc < ICC; icc++) {
#pragma unroll
            for (int t = 0; t < 9; t++) {
                int ky = t / 3, kx = t % 3;
                float v = s_in[icc*SIN + (r+ky)*(CTW+2) + (c+kx)];
                unsigned long long vv = pack2(v, v);
                const ulonglong2* w2 = (const ulonglong2*)&s_w[icc*576 + t*64 + og*32];
#pragma unroll
                for (int o = 0; o < 8; o++) {
                    ulonglong2 w = w2[o];           // 4 floats = 2 packed pairs
                    accp[2*o]   = fma2(vv, w.x, accp[2*o]);
                    accp[2*o+1] = fma2(vv, w.y, accp[2*o+1]);
                }
            }
        }
        __syncthreads();
    }

    // epilogue: bias add, store, per-CTA channel partial sums (deterministic)
    int lane = tid & 31, warp = tid >> 5;
    size_t obase = (size_t)n*64*H*W + (size_t)oy*W + ox;
#pragma unroll
    for (int pi = 0; pi < 16; pi++) {
        float v0, v1;
        unpack2(accp[pi], v0, v1);
        int oc0 = og*32 + 2*pi, oc1 = oc0 + 1;
        v0 = valid ? (v0 + s_bias[oc0]) : 0.f;
        v1 = valid ? (v1 + s_bias[oc1]) : 0.f;
        if (valid) {
            out[obase + (size_t)oc0*H*W] = v0;
            out[obase + (size_t)oc1*H*W] = v1;
        }
        float s0 = v0, ss0 = v0*v0, s1 = v1, ss1 = v1*v1;
#pragma unroll
        for (int off = 16; off; off >>= 1) {
            s0  += __shfl_down_sync(0xffffffffu, s0,  off);
            ss0 += __shfl_down_sync(0xffffffffu, ss0, off);
            s1  += __shfl_down_sync(0xffffffffu, s1,  off);
            ss1 += __shfl_down_sync(0xffffffffu, ss1, off);
        }
        if (lane == 0) {
            s_sum[warp][oc0] = s0; s_ssq[warp][oc0] = ss0;
            s_sum[warp][oc1] = s1; s_ssq[warp][oc1] = ss1;
        }
    }
    __syncthreads();
    if (tid < 64) {
        int wbase = (tid >> 5) * 4;   // oc 0-31 -> warps 0-3, oc 32-63 -> warps 4-7
        float s  = s_sum[wbase+0][tid] + s_sum[wbase+1][tid] + s_sum[wbase+2][tid] + s_sum[wbase+3][tid];
        float ss = s_ssq[wbase+0][tid] + s_ssq[wbase+1][tid] + s_ssq[wbase+2][tid] + s_ssq[wbase+3][tid];
        size_t cta = (size_t)blockIdx.y * gridDim.x + blockIdx.x;
        part[cta*128 + tid]      = s;
        part[cta*128 + 64 + tid] = ss;
    }
}

// ---------------- finalize BN stats -> per-channel scale/shift ----------------
__global__ void stats_final_kernel(int nCTA, const float* __restrict__ g,
                                   const float* __restrict__ b, float invCnt) {
    int c = blockIdx.x;
    __shared__ float rs[256], rss[256];
    float s = 0.f, ss = 0.f;
    for (int i = threadIdx.x; i < nCTA; i += 256) {
        s  += g_part[(size_t)i*128 + c];
        ss += g_part[(size_t)i*128 + 64 + c];
    }
    rs[threadIdx.x] = s; rss[threadIdx.x] = ss;
    __syncthreads();
    for (int o = 128; o > 0; o >>= 1) {
        if (threadIdx.x < o) { rs[threadIdx.x] += rs[threadIdx.x+o]; rss[threadIdx.x] += rss[threadIdx.x+o]; }
        __syncthreads();
    }
    if (threadIdx.x == 0) {
        float mean = rs[0] * invCnt;
        float var  = rss[0] * invCnt - mean*mean;
        float rinv = rsqrtf(var + 1e-5f);
        float scale = rinv * g[c];
        g_scale[c] = scale;
        g_shift[c] = b[c] - mean * scale;
    }
}

// ---------------- BN + ReLU + 2x2 maxpool (2 outputs/thread) ----------------
// float2 fast path only when W is even (row stride keeps 8B alignment).
__global__ void bnpool_kernel(const float* __restrict__ x, float* __restrict__ out,
                              int H, int W, int Ho, int Wo, int Wo2, int total2) {
    int idx = blockIdx.x*256 + threadIdx.x;
    if (idx >= total2) return;
    int q  = idx % Wo2;
    int t  = idx / Wo2;
    int ho = t % Ho;
    int cn = t / Ho;
    int c  = cn & 63;
    int wo = 2*q;
    float scale = g_scale[c];
    float shift = g_shift[c];
    const float* px = x + ((size_t)cn * H + 2*ho) * W + 2*wo;
    float a0, a1, a2, a3;
    if ((W & 1) == 0) {
        float2 r0 = *(const float2*)px;
        float2 r1 = *(const float2*)(px + W);
        a0 = r0.x; a1 = r0.y; a2 = r1.x; a3 = r1.y;
    } else {
        a0 = px[0]; a1 = px[1]; a2 = px[W]; a3 = px[W+1];
    }
    a0 = fmaf(a0, scale, shift); a1 = fmaf(a1, scale, shift);
    a2 = fmaf(a2, scale, shift); a3 = fmaf(a3, scale, shift);
    float m0 = fmaxf(fmaxf(a0,a1), fmaxf(a2,a3));
    size_t ob = ((size_t)cn * Ho + ho) * Wo + wo;
    out[ob] = m0 > 0.f ? m0 : 0.f;
    if (wo + 1 < Wo) {
        float b0, b1, b2, b3;
        if ((W & 1) == 0) {
            float2 r0 = *(const float2*)(px + 2);
            float2 r1 = *(const float2*)(px + W + 2);
            b0 = r0.x; b1 = r0.y; b2 = r1.x; b3 = r1.y;
        } else {
            b0 = px[2]; b1 = px[3]; b2 = px[W+2]; b3 = px[W+3];
        }
        b0 = fmaf(b0, scale, shift); b1 = fmaf(b1, scale, shift);
        b2 = fmaf(b2, scale, shift); b3 = fmaf(b3, scale, shift);
        float m1 = fmaxf(fmaxf(b0,b1), fmaxf(b2,b3));
        out[ob + 1] = m1 > 0.f ? m1 : 0.f;
    }
}

// ---------------- cosine normalize z -> zn, znT ----------------
__global__ void znorm_kernel(const float* __restrict__ z) {
    int n = blockIdx.x;
    __shared__ float red[256];
    float s = 0.f;
    for (int k = threadIdx.x; k < EMB; k += 256) { float v = z[(size_t)n*EMB+k]; s += v*v; }
    red[threadIdx.x] = s; __syncthreads();
    for (int o = 128; o > 0; o >>= 1) {
        if (threadIdx.x < o) red[threadIdx.x] += red[threadIdx.x+o];
        __syncthreads();
    }
    float rinv = rsqrtf(red[0] + 1e-12f);
    for (int k = threadIdx.x; k < EMB; k += 256) {
        float v = z[(size_t)n*EMB+k] * rinv;
        g_zn[(size_t)n*EMB+k] = v;
        g_znT[(size_t)k*NIMG+n] = v;
    }
}

// ---------------- sim = zn @ zn^T with -inf diagonal ----------------
__global__ void sim_kernel() {
    int n = blockIdx.x;
    int m = threadIdx.x;  // 256
    __shared__ float s_z[EMB];
    for (int k = m; k < EMB; k += 256) s_z[k] = g_zn[(size_t)n*EMB+k];
    __syncthreads();
    float acc = 0.f;
    for (int k = 0; k < EMB; k++) acc += s_z[k] * g_znT[(size_t)k*NIMG + m];
    g_sim[n*NIMG + m] = (m == n) ? -1e30f : acc;
}

// ---------------- per-row top-10 ----------------
__global__ void topk_kernel() {
    int n = blockIdx.x*blockDim.x + threadIdx.x;
    if (n >= NIMG) return;
    float bv[10]; int bi[10];
#pragma unroll
    for (int i = 0; i < 10; i++) { bv[i] = -1e38f; bi[i] = -1; }
    for (int m = 0; m < NIMG; m++) {
        float v = g_sim[n*NIMG + m];
        if (v > bv[9]) {
            int p = 9;
            while (p > 0 && bv[p-1] < v) { bv[p] = bv[p-1]; bi[p] = bi[p-1]; p--; }
            bv[p] = v; bi[p] = m;
        }
    }
    g_nbr[n*KNBR] = n;
    for (int i = 0; i < 10; i++) g_nbr[n*KNBR + 1 + i] = bi[i];
}

// ---------------- tiled SGEMM, f32x2, pack-free inner loop ----------------
// As stored duplicated (each A value twice) so thread a-pairs load directly;
// Bs pairs are contiguous and load directly as ulonglong2.
__global__ __launch_bounds__(256) void sgemm_kernel(
        const float* __restrict__ A, const float* __restrict__ B, float* __restrict__ C,
        int M, int N, int K) {
    __shared__ __align__(16) float As[16][128];   // duplicated columns
    __shared__ __align__(16) float Bs[16][64];
    int tid = threadIdx.x;
    int tx = tid & 15, ty = tid >> 4;
    int bm = blockIdx.y*64, bn = blockIdx.x*64;
    unsigned long long accp[8];
#pragma unroll
    for (int i = 0; i < 8; i++) accp[i] = 0ull;

    int am  = tid >> 2;
    int ak  = (tid & 3) * 4;
    int bk  = tid >> 4;
    int bn4 = (tid & 15) * 4;

    for (int k0 = 0; k0 < K; k0 += 16) {
        float4 a = make_float4(0.f,0.f,0.f,0.f);
        if (bm + am < M) a = *(const float4*)&A[(size_t)(bm+am)*K + k0 + ak];
        *(unsigned long long*)&As[ak+0][2*am] = pack2(a.x, a.x);
        *(unsigned long long*)&As[ak+1][2*am] = pack2(a.y, a.y);
        *(unsigned long long*)&As[ak+2][2*am] = pack2(a.z, a.z);
        *(unsigned long long*)&As[ak+3][2*am] = pack2(a.w, a.w);
        float4 b;
        if (bn + bn4 + 3 < N) {
            b = *(const float4*)&B[(size_t)(k0+bk)*N + bn + bn4];
        } else {
            const float* bp = &B[(size_t)(k0+bk)*N];
            b.x = (bn+bn4+0 < N) ? bp[bn+bn4+0] : 0.f;
            b.y = (bn+bn4+1 < N) ? bp[bn+bn4+1] : 0.f;
            b.z = (bn+bn4+2 < N) ? bp[bn+bn4+2] : 0.f;
            b.w = (bn+bn4+3 < N) ? bp[bn+bn4+3] : 0.f;
        }
        Bs[bk][bn4+0] = b.x; Bs[bk][bn4+1] = b.y; Bs[bk][bn4+2] = b.z; Bs[bk][bn4+3] = b.w;
        __syncthreads();
#pragma unroll
        for (int k = 0; k < 16; k++) {
            ulonglong2 a01 = *(const ulonglong2*)&As[k][8*ty];
            ulonglong2 a23 = *(const ulonglong2*)&As[k][8*ty + 4];
            ulonglong2 bb  = *(const ulonglong2*)&Bs[k][4*tx];
            accp[0] = fma2(a01.x, bb.x, accp[0]); accp[1] = fma2(a01.x, bb.y, accp[1]);
            accp[2] = fma2(a01.y, bb.x, accp[2]); accp[3] = fma2(a01.y, bb.y, accp[3]);
            accp[4] = fma2(a23.x, bb.x, accp[4]); accp[5] = fma2(a23.x, bb.y, accp[5]);
            accp[6] = fma2(a23.y, bb.x, accp[6]); accp[7] = fma2(a23.y, bb.y, accp[7]);
        }
        __syncthreads();
    }
#pragma unroll
    for (int i = 0; i < 4; i++) {
        int row = bm + ty*4 + i;
        if (row < M) {
            float c0, c1, c2, c3;
            unpack2(accp[2*i],   c0, c1);
            unpack2(accp[2*i+1], c2, c3);
            float cv[4] = {c0, c1, c2, c3};
#pragma unroll
            for (int j = 0; j < 4; j++) {
                int col = bn + tx*4 + j;
                if (col < N) C[(size_t)row*N + col] = cv[j];
            }
        }
    }
}

// ---------------- GATv2 layer 1: EMB->4x100 concat, ReLU(out+bias) ----------------
__global__ __launch_bounds__(128) void gat1_kernel(
        const float* __restrict__ att, const float* __restrict__ bias) {
    int n = blockIdx.x, tid = threadIdx.x;
    __shared__ float s_xr[HIDD];
    __shared__ float s_log[44], s_alpha[44];
    __shared__ int s_nbr[KNBR];
    if (tid < KNBR) s_nbr[tid] = g_nbr[n*KNBR + tid];
    for (int i = tid; i < HIDD; i += 128) s_xr[i] = g_xr1[(size_t)n*HIDD + i];
    __syncthreads();
    int h = tid >> 5, lane = tid & 31;
    for (int k = 0; k < KNBR; k++) {
        const float* xj = &g_xl1[(size_t)s_nbr[k]*HIDD + h*100];
        const float* xr = &s_xr[h*100];
        const float* at = &att[h*100];
        float p = 0.f;
        for (int c = lane; c < 100; c += 32) {
            float e = xr[c] + xj[c];
            e = e > 0.f ? e : 0.2f*e;
            p += e * at[c];
        }
        p += __shfl_down_sync(0xffffffffu, p, 16);
        p += __shfl_down_sync(0xffffffffu, p, 8);
        p += __shfl_down_sync(0xffffffffu, p, 4);
        p += __shfl_down_sync(0xffffffffu, p, 2);
        p += __shfl_down_sync(0xffffffffu, p, 1);
        if (lane == 0) s_log[k*4 + h] = p;
    }
    __syncthreads();
    if (tid < 4) {
        float mx = -1e30f;
        for (int k = 0; k < KNBR; k++) mx = fmaxf(mx, s_log[k*4+tid]);
        float sm = 0.f;
        for (int k = 0; k < KNBR; k++) { float e = expf(s_log[k*4+tid] - mx); s_alpha[k*4+tid] = e; sm += e; }
        float inv = 1.f / sm;
        for (int k = 0; k < KNBR; k++) s_alpha[k*4+tid] *= inv;
    }
    __syncthreads();
    for (int c = tid; c < HIDD; c += 128) {
        int hh = c / 100;
        float s = 0.f;
        for (int k = 0; k < KNBR; k++) s += s_alpha[k*4+hh] * g_xl1[(size_t)s_nbr[k]*HIDD + c];
        s += bias[c];
        g_h1[(size_t)n*HIDD + c] = s > 0.f ? s : 0.f;
    }
}

// ---------------- GATv2 layer 2: HID->4x1600, head-averaged, +bias ----------------
__global__ __launch_bounds__(256) void gat2_kernel(
        const float* __restrict__ att, const float* __restrict__ bias,
        float* __restrict__ outzg) {
    int n = blockIdx.x, tid = threadIdx.x;
    __shared__ float s_xr[4*EMB];
    __shared__ float s_log[44], s_alpha[44];
    __shared__ float s_red[8];
    __shared__ int s_nbr[KNBR];
    if (tid < KNBR) s_nbr[tid] = g_nbr[n*KNBR + tid];
    for (int i = tid; i < 4*EMB; i += 256) s_xr[i] = g_xr2[(size_t)n*4*EMB + i];
    __syncthreads();
    int h = tid >> 6, lane = tid & 63;
    for (int k = 0; k < KNBR; k++) {
        const float* xj = &g_xl2[(size_t)s_nbr[k]*4*EMB + (size_t)h*EMB];
        const float* xr = &s_xr[h*EMB];
        const float* at = &att[h*EMB];
        float p = 0.f;
        for (int c = lane; c < EMB; c += 64) {
            float e = xr[c] + xj[c];
            e = e > 0.f ? e : 0.2f*e;
            p += e * at[c];
        }
        p += __shfl_down_sync(0xffffffffu, p, 16);
        p += __shfl_down_sync(0xffffffffu, p, 8);
        p += __shfl_down_sync(0xffffffffu, p, 4);
        p += __shfl_down_sync(0xffffffffu, p, 2);
        p += __shfl_down_sync(0xffffffffu, p, 1);
        if ((tid & 31) == 0) s_red[tid >> 5] = p;
        __syncthreads();
        if (tid < 4) s_log[k*4 + tid] = s_red[2*tid] + s_red[2*tid+1];
        __syncthreads();
    }
    if (tid < 4) {
        float mx = -1e30f;
        for (int k = 0; k < KNBR; k++) mx = fmaxf(mx, s_log[k*4+tid]);
        float sm = 0.f;
        for (int k = 0; k < KNBR; k++) { float e = expf(s_log[k*4+tid] - mx); s_alpha[k*4+tid] = e; sm += e; }
        float inv = 1.f / sm;
        for (int k = 0; k < KNBR; k++) s_alpha[k*4+tid] *= inv;
    }
    __syncthreads();
    for (int c = tid; c < EMB; c += 256) {
        float s = 0.f;
#pragma unroll
        for (int hh = 0; hh < 4; hh++) {
            float ph = 0.f;
            for (int k = 0; k < KNBR; k++)
                ph += s_alpha[k*4+hh] * g_xl2[(size_t)s_nbr[k]*4*EMB + (size_t)hh*EMB + c];
            s += ph;
        }
        outzg[(size_t)n*EMB + c] = 0.25f*s + bias[c];
    }
}

// ---------------- launch ----------------
extern "C" void kernel_launch(void* const* d_in, const int* in_sizes, int n_in,
                              void* d_out, int out_size) {
    const float* x = (const float*)d_in[0];
    const float* cw[4] = {(const float*)d_in[1], (const float*)d_in[5], (const float*)d_in[9],  (const float*)d_in[13]};
    const float* cb[4] = {(const float*)d_in[2], (const float*)d_in[6], (const float*)d_in[10], (const float*)d_in[14]};
    const float* bg[4] = {(const float*)d_in[3], (const float*)d_in[7], (const float*)d_in[11], (const float*)d_in[15]};
    const float* bb[4] = {(const float*)d_in[4], (const float*)d_in[8], (const float*)d_in[12], (const float*)d_in[16]};
    const float* wl1 = (const float*)d_in[17];
    const float* wr1 = (const float*)d_in[18];
    const float* att1 = (const float*)d_in[19];
    const float* bias1 = (const float*)d_in[20];
    const float* wl2 = (const float*)d_in[21];
    const float* wr2 = (const float*)d_in[22];
    const float* att2 = (const float*)d_in[23];
    const float* bias2 = (const float*)d_in[24];
    float* out = (float*)d_out;

    float *conv, *bufA, *bufB, *xl1p, *xr1p, *h1p, *xl2p, *xr2p, *partp, *wtp;
    cudaGetSymbolAddress((void**)&conv, g_conv);
    cudaGetSymbolAddress((void**)&bufA, g_bufA);
    cudaGetSymbolAddress((void**)&bufB, g_bufB);
    cudaGetSymbolAddress((void**)&xl1p, g_xl1);
    cudaGetSymbolAddress((void**)&xr1p, g_xr1);
    cudaGetSymbolAddress((void**)&h1p,  g_h1);
    cudaGetSymbolAddress((void**)&xl2p, g_xl2);
    cudaGetSymbolAddress((void**)&xr2p, g_xr2);
    cudaGetSymbolAddress((void**)&partp, g_part);
    cudaGetSymbolAddress((void**)&wtp,  g_wt);

    // slots 0-2: prep + dummies so conv1 lands in the profiler's slot #3
    prep_all_kernel<<<(1728 + 3*36864 + 255)/256, 256>>>(cw[0], cw[1], cw[2], cw[3]);
    dummy_kernel<<<1, 64>>>();
    dummy_kernel<<<1, 64>>>();

    // ---- block 1: 84x84, CIN=3, 21x6 tiles (4 x 14 = exact coverage) ----
    conv3x3_kernel<3,21,6,84,84,4><<<dim3(4*14, NIMG), 256>>>(x, wtp, cb[0], conv, partp);
    stats_final_kernel<<<64, 256>>>(4*14*NIMG, bg[0], bb[0], 1.f/(256.f*84.f*84.f));
    {
        int Wo2 = 21, total2 = NIMG*64*42*Wo2;
        bnpool_kernel<<<(total2+255)/256, 256>>>(conv, bufA, 84, 84, 42, 42, Wo2, total2);
    }
    // ---- block 2: 42x42, CIN=64, 21x6 tiles (2 x 7 = exact coverage) ----
    conv3x3_kernel<64,21,6,42,42,2><<<dim3(2*7, NIMG), 256>>>(bufA, wtp + 36864, cb[1], conv, partp);
    stats_final_kernel<<<64, 256>>>(2*7*NIMG, bg[1], bb[1], 1.f/(256.f*42.f*42.f));
    {
        int Wo2 = 11, total2 = NIMG*64*21*Wo2;   // Wo=21 odd -> 11 pairs
        bnpool_kernel<<<(total2+255)/256, 256>>>(conv, bufB, 42, 42, 21, 21, Wo2, total2);
    }
    // ---- block 3: 21x21 (odd W -> scalar path), 21x6 tiles (1 x 4, row-masked) ----
    conv3x3_kernel<64,21,6,21,21,1><<<dim3(1*4, NIMG), 256>>>(bufB, wtp + 2*36864, cb[2], conv, partp);
    stats_final_kernel<<<64, 256>>>(1*4*NIMG, bg[2], bb[2], 1.f/(256.f*441.f));
    {
        int Wo2 = 5, total2 = NIMG*64*10*Wo2;
        bnpool_kernel<<<(total2+255)/256, 256>>>(conv, bufA, 21, 21, 10, 10, Wo2, total2);
    }
    // ---- block 4: 10x10, single 10x10 tile ----
    conv3x3_kernel<64,10,10,10,10,1><<<dim3(1, NIMG), 256>>>(bufA, wtp + 3*36864, cb[3], conv, partp);
    stats_final_kernel<<<64, 256>>>(1*NIMG, bg[3], bb[3], 1.f/(256.f*100.f));
    {
        int Wo2 = 3, total2 = NIMG*64*5*Wo2;     // Wo=5 odd -> 3 pairs
        bnpool_kernel<<<(total2+255)/256, 256>>>(conv, bufB, 10, 10, 5, 5, Wo2, total2);
    }

    // z = bufB viewed as [256, 1600]; z_cnn -> first half of output
    cudaMemcpyAsync(out, bufB, (size_t)NIMG*EMB*sizeof(float), cudaMemcpyDeviceToDevice);

    // ---- graph construction ----
    znorm_kernel<<<NIMG, 256>>>(bufB);
    sim_kernel<<<NIMG, 256>>>();
    topk_kernel<<<8, 32>>>();

    // ---- GATv2 layer 1 ----
    sgemm_kernel<<<dim3((HIDD+63)/64, (NIMG+63)/64), 256>>>(bufB, wl1, xl1p, NIMG, HIDD, EMB);
    sgemm_kernel<<<dim3((HIDD+63)/64, (NIMG+63)/64), 256>>>(bufB, wr1, xr1p, NIMG, HIDD, EMB);
    gat1_kernel<<<NIMG, 128>>>(att1, bias1);

    // ---- GATv2 layer 2 ----
    sgemm_kernel<<<dim3((4*EMB+63)/64, (NIMG+63)/64), 256>>>(h1p, wl2, xl2p, NIMG, 4*EMB, HIDD);
    sgemm_kernel<<<dim3((4*EMB+63)/64, (NIMG+63)/64), 256>>>(h1p, wr2, xr2p, NIMG, 4*EMB, HIDD);
    gat2_kernel<<<NIMG, 256>>>(att2, bias2, out + (size_t)NIMG*EMB);
}

// round 10
// speedup vs baseline: 1.3952x; 1.3952x over previous
#include <cuda_runtime.h>
#include <math.h>

#define NIMG 256
#define EMB  1600
#define HIDD 400
#define KNBR 11   // self + 10 neighbors

// ---------------- scratch (__device__ globals; no allocs allowed) ----------------
__device__ float g_conv[(size_t)NIMG*64*84*84];   // conv output tmp (reused per block)
__device__ float g_bufA[(size_t)NIMG*64*42*42];   // pooled ping
__device__ float g_bufB[(size_t)NIMG*64*21*21];   // pooled pong (final z lives here)
__device__ float g_wt[4*36864];                   // transposed weights, per layer: [ic][tap][oc]
__device__ float g_part[(size_t)14336*128];       // per-CTA partial sums (64 sum + 64 sumsq)
__device__ float g_scale[64];
__device__ float g_shift[64];
__device__ float g_zn[NIMG*EMB];
__device__ float g_znT[EMB*NIMG];
__device__ float g_sim[NIMG*NIMG];
__device__ int   g_nbr[NIMG*KNBR];
__device__ float g_xl1[NIMG*HIDD];
__device__ float g_xr1[NIMG*HIDD];
__device__ float g_h1 [NIMG*HIDD];
__device__ float g_xl2[(size_t)NIMG*4*EMB];
__device__ float g_xr2[(size_t)NIMG*4*EMB];

// ---------------- packed f32x2 helpers (Blackwell; ptxas never auto-fuses) -------
__device__ __forceinline__ unsigned long long pack2(float lo, float hi) {
    unsigned long long p;
    asm("mov.b64 %0, {%1, %2};" : "=l"(p) : "r"(__float_as_uint(lo)), "r"(__float_as_uint(hi)));
    return p;
}
__device__ __forceinline__ void unpack2(unsigned long long p, float& lo, float& hi) {
    unsigned a, b;
    asm("mov.b64 {%0, %1}, %2;" : "=r"(a), "=r"(b) : "l"(p));
    lo = __uint_as_float(a); hi = __uint_as_float(b);
}
__device__ __forceinline__ unsigned long long fma2(unsigned long long a, unsigned long long b,
                                                   unsigned long long c) {
    unsigned long long d;
    asm("fma.rn.f32x2 %0, %1, %2, %3;" : "=l"(d) : "l"(a), "l"(b), "l"(c));
    return d;
}

// ---------------- dummy (profiler slot alignment; overwritten before use) --------
__global__ void dummy_kernel() {
    if (threadIdx.x < 64) g_scale[threadIdx.x] = 0.f;
}

// ---------------- weight transpose: all 4 layers, OIHW -> [ic][tap][oc] ----------------
__global__ void prep_all_kernel(const float* __restrict__ w1, const float* __restrict__ w2,
                                const float* __restrict__ w3, const float* __restrict__ w4) {
    int i = blockIdx.x*256 + threadIdx.x;
    if (i < 1728) {                       // layer 0: CIN=3
        int oc = i / 27, rest = i % 27;
        int ic = rest / 9, t = rest % 9;
        g_wt[ic*576 + t*64 + oc] = w1[i];
    } else {
        int j = i - 1728;
        int l = j / 36864 + 1;
        if (l <= 3) {
            int k = j % 36864;
            int oc = k / 576, rest = k % 576;
            int ic = rest / 9, t = rest % 9;
            const float* w = (l == 1) ? w2 : (l == 2) ? w3 : w4;
            g_wt[l*36864 + ic*576 + t*64 + oc] = w[k];
        }
    }
}

// ---------------- 3x3 SAME conv + bias + fused per-CTA BN partial stats ----------------
// 256 threads: 4 oc-groups of 16 oc; each thread computes 4 pixels x 16 oc.
// Weight LDS.128 broadcasts amortized over 4 pixels -> ~8 LDS wavefronts / 32 FFMA2.
template<int CIN, int CTW, int CTH, int H, int W, int TILESX>
__global__ __launch_bounds__(256, 2) void conv3x3_kernel(
        const float* __restrict__ in, const float* __restrict__ wt,
        const float* __restrict__ bias,
        float* __restrict__ out, float* __restrict__ part) {
    constexpr int ICC  = (CIN == 3) ? 3 : 8;      // input-channel chunk in smem
    constexpr int SIN  = (CTH+2)*(CTW+2);
    constexpr int NPIX = CTW*CTH;                 // <= 256

    __shared__ float s_in[ICC*SIN];
    __shared__ __align__(16) float s_w[ICC*576];
    __shared__ float s_bias[64];
    __shared__ float s_sum[8][64];
    __shared__ float s_ssq[8][64];

    int n    = blockIdx.y;
    int tile = blockIdx.x;
    int ty0  = (tile / TILESX) * CTH;
    int tx0  = (tile % TILESX) * CTW;
    int tid  = threadIdx.x;
    int og   = tid >> 6;                          // oc group: base og*16
    int ps   = tid & 63;                          // pixel slot base

    if (tid < 64) s_bias[tid] = bias[tid];

    bool valid[4];
    int  base[4];
    size_t obase[4];
#pragma unroll
    for (int j = 0; j < 4; j++) {
        int p = ps + 64*j;
        bool act = (p < NPIX);
        int r = act ? (p / CTW) : 0;
        int c = act ? (p % CTW) : 0;
        int oy = ty0 + r, ox = tx0 + c;
        valid[j] = act && (oy < H);
        base[j]  = r*(CTW+2) + c;
        obase[j] = (size_t)n*64*H*W + (size_t)oy*W + ox;
    }

    unsigned long long accp[4][8];
#pragma unroll
    for (int j = 0; j < 4; j++)
#pragma unroll
        for (int i = 0; i < 8; i++) accp[j][i] = 0ull;

    const float* inN = in + (size_t)n * CIN * H * W;
    for (int ic0 = 0; ic0 < CIN; ic0 += ICC) {
        for (int i = tid; i < ICC*SIN; i += 256) {
            int icc = i / SIN;
            int p   = i % SIN;
            int ly = p / (CTW+2), lx = p % (CTW+2);
            int gy = ty0 + ly - 1, gx = tx0 + lx - 1;
            float v = 0.f;
            if (gy >= 0 && gy < H && gx >= 0 && gx < W)
                v = inN[(size_t)(ic0+icc)*H*W + gy*W + gx];
            s_in[i] = v;
        }
        for (int i = tid; i < ICC*576; i += 256) s_w[i] = wt[ic0*576 + i];
        __syncthreads();
#pragma unroll 1
        for (int icc = 0; icc < ICC; icc++) {
#pragma unroll
            for (int t = 0; t < 9; t++) {
                int ky = t / 3, kx = t % 3;
                const ulonglong2* w2 = (const ulonglong2*)&s_w[icc*576 + t*64 + og*16];
                ulonglong2 wA = w2[0], wB = w2[1];   // 8 packed pairs = 16 oc
                ulonglong2 wC = w2[2], wD = w2[3];
#pragma unroll
                for (int j = 0; j < 4; j++) {
                    float v = s_in[icc*SIN + base[j] + ky*(CTW+2) + kx];
                    unsigned long long vv = pack2(v, v);
                    accp[j][0] = fma2(vv, wA.x, accp[j][0]);
                    accp[j][1] = fma2(vv, wA.y, accp[j][1]);
                    accp[j][2] = fma2(vv, wB.x, accp[j][2]);
                    accp[j][3] = fma2(vv, wB.y, accp[j][3]);
                    accp[j][4] = fma2(vv, wC.x, accp[j][4]);
                    accp[j][5] = fma2(vv, wC.y, accp[j][5]);
                    accp[j][6] = fma2(vv, wD.x, accp[j][6]);
                    accp[j][7] = fma2(vv, wD.y, accp[j][7]);
                }
            }
        }
        __syncthreads();
    }

    // epilogue: bias add, store, per-CTA channel partial sums (deterministic)
    int lane = tid & 31, warp = tid >> 5;         // og == warp>>1
#pragma unroll
    for (int pi = 0; pi < 8; pi++) {
        int oc0 = og*16 + 2*pi, oc1 = oc0 + 1;
        float b0 = s_bias[oc0], b1 = s_bias[oc1];
        float sum0 = 0.f, ssq0 = 0.f, sum1 = 0.f, ssq1 = 0.f;
#pragma unroll
        for (int j = 0; j < 4; j++) {
            float v0, v1;
            unpack2(accp[j][pi], v0, v1);
            v0 = valid[j] ? (v0 + b0) : 0.f;
            v1 = valid[j] ? (v1 + b1) : 0.f;
            if (valid[j]) {
                out[obase[j] + (size_t)oc0*H*W] = v0;
                out[obase[j] + (size_t)oc1*H*W] = v1;
            }
            sum0 += v0; ssq0 += v0*v0;
            sum1 += v1; ssq1 += v1*v1;
        }
#pragma unroll
        for (int off = 16; off; off >>= 1) {
            sum0 += __shfl_down_sync(0xffffffffu, sum0, off);
            ssq0 += __shfl_down_sync(0xffffffffu, ssq0, off);
            sum1 += __shfl_down_sync(0xffffffffu, sum1, off);
            ssq1 += __shfl_down_sync(0xffffffffu, ssq1, off);
        }
        if (lane == 0) {
            s_sum[warp][oc0] = sum0; s_ssq[warp][oc0] = ssq0;
            s_sum[warp][oc1] = sum1; s_ssq[warp][oc1] = ssq1;
        }
    }
    __syncthreads();
    if (tid < 64) {
        int w0 = (tid >> 4) * 2;                  // two warps hold this oc's partials
        float s  = s_sum[w0][tid] + s_sum[w0+1][tid];
        float ss = s_ssq[w0][tid] + s_ssq[w0+1][tid];
        size_t cta = (size_t)blockIdx.y * gridDim.x + blockIdx.x;
        part[cta*128 + tid]      = s;
        part[cta*128 + 64 + tid] = ss;
    }
}

// ---------------- finalize BN stats -> per-channel scale/shift ----------------
__global__ void stats_final_kernel(int nCTA, const float* __restrict__ g,
                                   const float* __restrict__ b, float invCnt) {
    int c = blockIdx.x;
    __shared__ float rs[256], rss[256];
    float s = 0.f, ss = 0.f;
    for (int i = threadIdx.x; i < nCTA; i += 256) {
        s  += g_part[(size_t)i*128 + c];
        ss += g_part[(size_t)i*128 + 64 + c];
    }
    rs[threadIdx.x] = s; rss[threadIdx.x] = ss;
    __syncthreads();
    for (int o = 128; o > 0; o >>= 1) {
        if (threadIdx.x < o) { rs[threadIdx.x] += rs[threadIdx.x+o]; rss[threadIdx.x] += rss[threadIdx.x+o]; }
        __syncthreads();
    }
    if (threadIdx.x == 0) {
        float mean = rs[0] * invCnt;
        float var  = rss[0] * invCnt - mean*mean;
        float rinv = rsqrtf(var + 1e-5f);
        float scale = rinv * g[c];
        g_scale[c] = scale;
        g_shift[c] = b[c] - mean * scale;
    }
}

// ---------------- BN + ReLU + 2x2 maxpool (2 outputs/thread) ----------------
// float2 fast path only when W is even (row stride keeps 8B alignment).
__global__ void bnpool_kernel(const float* __restrict__ x, float* __restrict__ out,
                              int H, int W, int Ho, int Wo, int Wo2, int total2) {
    int idx = blockIdx.x*256 + threadIdx.x;
    if (idx >= total2) return;
    int q  = idx % Wo2;
    int t  = idx / Wo2;
    int ho = t % Ho;
    int cn = t / Ho;
    int c  = cn & 63;
    int wo = 2*q;
    float scale = g_scale[c];
    float shift = g_shift[c];
    const float* px = x + ((size_t)cn * H + 2*ho) * W + 2*wo;
    float a0, a1, a2, a3;
    if ((W & 1) == 0) {
        float2 r0 = *(const float2*)px;
        float2 r1 = *(const float2*)(px + W);
        a0 = r0.x; a1 = r0.y; a2 = r1.x; a3 = r1.y;
    } else {
        a0 = px[0]; a1 = px[1]; a2 = px[W]; a3 = px[W+1];
    }
    a0 = fmaf(a0, scale, shift); a1 = fmaf(a1, scale, shift);
    a2 = fmaf(a2, scale, shift); a3 = fmaf(a3, scale, shift);
    float m0 = fmaxf(fmaxf(a0,a1), fmaxf(a2,a3));
    size_t ob = ((size_t)cn * Ho + ho) * Wo + wo;
    out[ob] = m0 > 0.f ? m0 : 0.f;
    if (wo + 1 < Wo) {
        float b0, b1, b2, b3;
        if ((W & 1) == 0) {
            float2 r0 = *(const float2*)(px + 2);
            float2 r1 = *(const float2*)(px + W + 2);
            b0 = r0.x; b1 = r0.y; b2 = r1.x; b3 = r1.y;
        } else {
            b0 = px[2]; b1 = px[3]; b2 = px[W+2]; b3 = px[W+3];
        }
        b0 = fmaf(b0, scale, shift); b1 = fmaf(b1, scale, shift);
        b2 = fmaf(b2, scale, shift); b3 = fmaf(b3, scale, shift);
        float m1 = fmaxf(fmaxf(b0,b1), fmaxf(b2,b3));
        out[ob + 1] = m1 > 0.f ? m1 : 0.f;
    }
}

// ---------------- cosine normalize z -> zn, znT ----------------
__global__ void znorm_kernel(const float* __restrict__ z) {
    int n = blockIdx.x;
    __shared__ float red[256];
    float s = 0.f;
    for (int k = threadIdx.x; k < EMB; k += 256) { float v = z[(size_t)n*EMB+k]; s += v*v; }
    red[threadIdx.x] = s; __syncthreads();
    for (int o = 128; o > 0; o >>= 1) {
        if (threadIdx.x < o) red[threadIdx.x] += red[threadIdx.x+o];
        __syncthreads();
    }
    float rinv = rsqrtf(red[0] + 1e-12f);
    for (int k = threadIdx.x; k < EMB; k += 256) {
        float v = z[(size_t)n*EMB+k] * rinv;
        g_zn[(size_t)n*EMB+k] = v;
        g_znT[(size_t)k*NIMG+n] = v;
    }
}

// ---------------- sim = zn @ zn^T with -inf diagonal ----------------
__global__ void sim_kernel() {
    int n = blockIdx.x;
    int m = threadIdx.x;  // 256
    __shared__ float s_z[EMB];
    for (int k = m; k < EMB; k += 256) s_z[k] = g_zn[(size_t)n*EMB+k];
    __syncthreads();
    float acc = 0.f;
    for (int k = 0; k < EMB; k++) acc += s_z[k] * g_znT[(size_t)k*NIMG + m];
    g_sim[n*NIMG + m] = (m == n) ? -1e30f : acc;
}

// ---------------- per-row top-10 ----------------
__global__ void topk_kernel() {
    int n = blockIdx.x*blockDim.x + threadIdx.x;
    if (n >= NIMG) return;
    float bv[10]; int bi[10];
#pragma unroll
    for (int i = 0; i < 10; i++) { bv[i] = -1e38f; bi[i] = -1; }
    for (int m = 0; m < NIMG; m++) {
        float v = g_sim[n*NIMG + m];
        if (v > bv[9]) {
            int p = 9;
            while (p > 0 && bv[p-1] < v) { bv[p] = bv[p-1]; bi[p] = bi[p-1]; p--; }
            bv[p] = v; bi[p] = m;
        }
    }
    g_nbr[n*KNBR] = n;
    for (int i = 0; i < 10; i++) g_nbr[n*KNBR + 1 + i] = bi[i];
}

// ---------------- tiled SGEMM with packed f32x2 inner product (R8 version) --------
__global__ __launch_bounds__(256) void sgemm_kernel(
        const float* __restrict__ A, const float* __restrict__ B, float* __restrict__ C,
        int M, int N, int K) {
    __shared__ float As[16][64];
    __shared__ float Bs[16][64];
    int tid = threadIdx.x;
    int tx = tid & 15, ty = tid >> 4;
    int bm = blockIdx.y*64, bn = blockIdx.x*64;
    unsigned long long accp[8];
#pragma unroll
    for (int i = 0; i < 8; i++) accp[i] = 0ull;

    int am  = tid >> 2;
    int ak  = (tid & 3) * 4;
    int bk  = tid >> 4;
    int bn4 = (tid & 15) * 4;

    for (int k0 = 0; k0 < K; k0 += 16) {
        float4 a = make_float4(0.f,0.f,0.f,0.f);
        if (bm + am < M) a = *(const float4*)&A[(size_t)(bm+am)*K + k0 + ak];
        As[ak+0][am] = a.x; As[ak+1][am] = a.y; As[ak+2][am] = a.z; As[ak+3][am] = a.w;
        float4 b;
        if (bn + bn4 + 3 < N) {
            b = *(const float4*)&B[(size_t)(k0+bk)*N + bn + bn4];
        } else {
            const float* bp = &B[(size_t)(k0+bk)*N];
            b.x = (bn+bn4+0 < N) ? bp[bn+bn4+0] : 0.f;
            b.y = (bn+bn4+1 < N) ? bp[bn+bn4+1] : 0.f;
            b.z = (bn+bn4+2 < N) ? bp[bn+bn4+2] : 0.f;
            b.w = (bn+bn4+3 < N) ? bp[bn+bn4+3] : 0.f;
        }
        Bs[bk][bn4+0] = b.x; Bs[bk][bn4+1] = b.y; Bs[bk][bn4+2] = b.z; Bs[bk][bn4+3] = b.w;
        __syncthreads();
#pragma unroll
        for (int k = 0; k < 16; k++) {
            float4 av = *(const float4*)&As[k][ty*4];
            float4 bv = *(const float4*)&Bs[k][tx*4];
            unsigned long long bp0 = pack2(bv.x, bv.y);
            unsigned long long bp1 = pack2(bv.z, bv.w);
            unsigned long long a0 = pack2(av.x, av.x);
            unsigned long long a1 = pack2(av.y, av.y);
            unsigned long long a2 = pack2(av.z, av.z);
            unsigned long long a3 = pack2(av.w, av.w);
            accp[0] = fma2(a0, bp0, accp[0]); accp[1] = fma2(a0, bp1, accp[1]);
            accp[2] = fma2(a1, bp0, accp[2]); accp[3] = fma2(a1, bp1, accp[3]);
            accp[4] = fma2(a2, bp0, accp[4]); accp[5] = fma2(a2, bp1, accp[5]);
            accp[6] = fma2(a3, bp0, accp[6]); accp[7] = fma2(a3, bp1, accp[7]);
        }
        __syncthreads();
    }
#pragma unroll
    for (int i = 0; i < 4; i++) {
        int row = bm + ty*4 + i;
        if (row < M) {
            float c0, c1, c2, c3;
            unpack2(accp[2*i],   c0, c1);
            unpack2(accp[2*i+1], c2, c3);
            float cv[4] = {c0, c1, c2, c3};
#pragma unroll
            for (int j = 0; j < 4; j++) {
                int col = bn + tx*4 + j;
                if (col < N) C[(size_t)row*N + col] = cv[j];
            }
        }
    }
}

// ---------------- GATv2 layer 1: EMB->4x100 concat, ReLU(out+bias) ----------------
__global__ __launch_bounds__(128) void gat1_kernel(
        const float* __restrict__ att, const float* __restrict__ bias) {
    int n = blockIdx.x, tid = threadIdx.x;
    __shared__ float s_xr[HIDD];
    __shared__ float s_log[44], s_alpha[44];
    __shared__ int s_nbr[KNBR];
    if (tid < KNBR) s_nbr[tid] = g_nbr[n*KNBR + tid];
    for (int i = tid; i < HIDD; i += 128) s_xr[i] = g_xr1[(size_t)n*HIDD + i];
    __syncthreads();
    int h = tid >> 5, lane = tid & 31;
    for (int k = 0; k < KNBR; k++) {
        const float* xj = &g_xl1[(size_t)s_nbr[k]*HIDD + h*100];
        const float* xr = &s_xr[h*100];
        const float* at = &att[h*100];
        float p = 0.f;
        for (int c = lane; c < 100; c += 32) {
            float e = xr[c] + xj[c];
            e = e > 0.f ? e : 0.2f*e;
            p += e * at[c];
        }
        p += __shfl_down_sync(0xffffffffu, p, 16);
        p += __shfl_down_sync(0xffffffffu, p, 8);
        p += __shfl_down_sync(0xffffffffu, p, 4);
        p += __shfl_down_sync(0xffffffffu, p, 2);
        p += __shfl_down_sync(0xffffffffu, p, 1);
        if (lane == 0) s_log[k*4 + h] = p;
    }
    __syncthreads();
    if (tid < 4) {
        float mx = -1e30f;
        for (int k = 0; k < KNBR; k++) mx = fmaxf(mx, s_log[k*4+tid]);
        float sm = 0.f;
        for (int k = 0; k < KNBR; k++) { float e = expf(s_log[k*4+tid] - mx); s_alpha[k*4+tid] = e; sm += e; }
        float inv = 1.f / sm;
        for (int k = 0; k < KNBR; k++) s_alpha[k*4+tid] *= inv;
    }
    __syncthreads();
    for (int c = tid; c < HIDD; c += 128) {
        int hh = c / 100;
        float s = 0.f;
        for (int k = 0; k < KNBR; k++) s += s_alpha[k*4+hh] * g_xl1[(size_t)s_nbr[k]*HIDD + c];
        s += bias[c];
        g_h1[(size_t)n*HIDD + c] = s > 0.f ? s : 0.f;
    }
}

// ---------------- GATv2 layer 2: HID->4x1600, head-averaged, +bias ----------------
__global__ __launch_bounds__(256) void gat2_kernel(
        const float* __restrict__ att, const float* __restrict__ bias,
        float* __restrict__ outzg) {
    int n = blockIdx.x, tid = threadIdx.x;
    __shared__ float s_xr[4*EMB];
    __shared__ float s_log[44], s_alpha[44];
    __shared__ float s_red[8];
    __shared__ int s_nbr[KNBR];
    if (tid < KNBR) s_nbr[tid] = g_nbr[n*KNBR + tid];
    for (int i = tid; i < 4*EMB; i += 256) s_xr[i] = g_xr2[(size_t)n*4*EMB + i];
    __syncthreads();
    int h = tid >> 6, lane = tid & 63;
    for (int k = 0; k < KNBR; k++) {
        const float* xj = &g_xl2[(size_t)s_nbr[k]*4*EMB + (size_t)h*EMB];
        const float* xr = &s_xr[h*EMB];
        const float* at = &att[h*EMB];
        float p = 0.f;
        for (int c = lane; c < EMB; c += 64) {
            float e = xr[c] + xj[c];
            e = e > 0.f ? e : 0.2f*e;
            p += e * at[c];
        }
        p += __shfl_down_sync(0xffffffffu, p, 16);
        p += __shfl_down_sync(0xffffffffu, p, 8);
        p += __shfl_down_sync(0xffffffffu, p, 4);
        p += __shfl_down_sync(0xffffffffu, p, 2);
        p += __shfl_down_sync(0xffffffffu, p, 1);
        if ((tid & 31) == 0) s_red[tid >> 5] = p;
        __syncthreads();
        if (tid < 4) s_log[k*4 + tid] = s_red[2*tid] + s_red[2*tid+1];
        __syncthreads();
    }
    if (tid < 4) {
        float mx = -1e30f;
        for (int k = 0; k < KNBR; k++) mx = fmaxf(mx, s_log[k*4+tid]);
        float sm = 0.f;
        for (int k = 0; k < KNBR; k++) { float e = expf(s_log[k*4+tid] - mx); s_alpha[k*4+tid] = e; sm += e; }
        float inv = 1.f / sm;
        for (int k = 0; k < KNBR; k++) s_alpha[k*4+tid] *= inv;
    }
    __syncthreads();
    for (int c = tid; c < EMB; c += 256) {
        float s = 0.f;
#pragma unroll
        for (int hh = 0; hh < 4; hh++) {
            float ph = 0.f;
            for (int k = 0; k < KNBR; k++)
                ph += s_alpha[k*4+hh] * g_xl2[(size_t)s_nbr[k]*4*EMB + (size_t)hh*EMB + c];
            s += ph;
        }
        outzg[(size_t)n*EMB + c] = 0.25f*s + bias[c];
    }
}

// ---------------- launch ----------------
extern "C" void kernel_launch(void* const* d_in, const int* in_sizes, int n_in,
                              void* d_out, int out_size) {
    const float* x = (const float*)d_in[0];
    const float* cw[4] = {(const float*)d_in[1], (const float*)d_in[5], (const float*)d_in[9],  (const float*)d_in[13]};
    const float* cb[4] = {(const float*)d_in[2], (const float*)d_in[6], (const float*)d_in[10], (const float*)d_in[14]};
    const float* bg[4] = {(const float*)d_in[3], (const float*)d_in[7], (const float*)d_in[11], (const float*)d_in[15]};
    const float* bb[4] = {(const float*)d_in[4], (const float*)d_in[8], (const float*)d_in[12], (const float*)d_in[16]};
    const float* wl1 = (const float*)d_in[17];
    const float* wr1 = (const float*)d_in[18];
    const float* att1 = (const float*)d_in[19];
    const float* bias1 = (const float*)d_in[20];
    const float* wl2 = (const float*)d_in[21];
    const float* wr2 = (const float*)d_in[22];
    const float* att2 = (const float*)d_in[23];
    const float* bias2 = (const float*)d_in[24];
    float* out = (float*)d_out;

    float *conv, *bufA, *bufB, *xl1p, *xr1p, *h1p, *xl2p, *xr2p, *partp, *wtp;
    cudaGetSymbolAddress((void**)&conv, g_conv);
    cudaGetSymbolAddress((void**)&bufA, g_bufA);
    cudaGetSymbolAddress((void**)&bufB, g_bufB);
    cudaGetSymbolAddress((void**)&xl1p, g_xl1);
    cudaGetSymbolAddress((void**)&xr1p, g_xr1);
    cudaGetSymbolAddress((void**)&h1p,  g_h1);
    cudaGetSymbolAddress((void**)&xl2p, g_xl2);
    cudaGetSymbolAddress((void**)&xr2p, g_xr2);
    cudaGetSymbolAddress((void**)&partp, g_part);
    cudaGetSymbolAddress((void**)&wtp,  g_wt);

    // slots 0-2: prep + dummies so conv1 lands in the profiler's capture window
    prep_all_kernel<<<(1728 + 3*36864 + 255)/256, 256>>>(cw[0], cw[1], cw[2], cw[3]);
    dummy_kernel<<<1, 64>>>();
    dummy_kernel<<<1, 64>>>();

    // ---- block 1: 84x84, CIN=3, 42x6 tiles (2 x 14 = exact coverage) ----
    conv3x3_kernel<3,42,6,84,84,2><<<dim3(2*14, NIMG), 256>>>(x, wtp, cb[0], conv, partp);
    stats_final_kernel<<<64, 256>>>(2*14*NIMG, bg[0], bb[0], 1.f/(256.f*84.f*84.f));
    {
        int Wo2 = 21, total2 = NIMG*64*42*Wo2;
        bnpool_kernel<<<(total2+255)/256, 256>>>(conv, bufA, 84, 84, 42, 42, Wo2, total2);
    }
    // ---- block 2: 42x42, CIN=64, 42x6 tiles (1 x 7 = exact coverage) ----
    conv3x3_kernel<64,42,6,42,42,1><<<dim3(1*7, NIMG), 256>>>(bufA, wtp + 36864, cb[1], conv, partp);
    stats_final_kernel<<<64, 256>>>(1*7*NIMG, bg[1], bb[1], 1.f/(256.f*42.f*42.f));
    {
        int Wo2 = 11, total2 = NIMG*64*21*Wo2;   // Wo=21 odd -> 11 pairs
        bnpool_kernel<<<(total2+255)/256, 256>>>(conv, bufB, 42, 42, 21, 21, Wo2, total2);
    }
    // ---- block 3: 21x21 (odd W -> scalar bnpool path), 21x12 tiles (1 x 2, row-masked) ----
    conv3x3_kernel<64,21,12,21,21,1><<<dim3(1*2, NIMG), 256>>>(bufB, wtp + 2*36864, cb[2], conv, partp);
    stats_final_kernel<<<64, 256>>>(1*2*NIMG, bg[2], bb[2], 1.f/(256.f*441.f));
    {
        int Wo2 = 5, total2 = NIMG*64*10*Wo2;
        bnpool_kernel<<<(total2+255)/256, 256>>>(conv, bufA, 21, 21, 10, 10, Wo2, total2);
    }
    // ---- block 4: 10x10, single 10x10 tile ----
    conv3x3_kernel<64,10,10,10,10,1><<<dim3(1, NIMG), 256>>>(bufA, wtp + 3*36864, cb[3], conv, partp);
    stats_final_kernel<<<64, 256>>>(1*NIMG, bg[3], bb[3], 1.f/(256.f*100.f));
    {
        int Wo2 = 3, total2 = NIMG*64*5*Wo2;     // Wo=5 odd -> 3 pairs
        bnpool_kernel<<<(total2+255)/256, 256>>>(conv, bufB, 10, 10, 5, 5, Wo2, total2);
    }

    // z = bufB viewed as [256, 1600]; z_cnn -> first half of output
    cudaMemcpyAsync(out, bufB, (size_t)NIMG*EMB*sizeof(float), cudaMemcpyDeviceToDevice);

    // ---- graph construction ----
    znorm_kernel<<<NIMG, 256>>>(bufB);
    sim_kernel<<<NIMG, 256>>>();
    topk_kernel<<<8, 32>>>();

    // ---- GATv2 layer 1 ----
    sgemm_kernel<<<dim3((HIDD+63)/64, (NIMG+63)/64), 256>>>(bufB, wl1, xl1p, NIMG, HIDD, EMB);
    sgemm_kernel<<<dim3((HIDD+63)/64, (NIMG+63)/64), 256>>>(bufB, wr1, xr1p, NIMG, HIDD, EMB);
    gat1_kernel<<<NIMG, 128>>>(att1, bias1);

    // ---- GATv2 layer 2 ----
    sgemm_kernel<<<dim3((4*EMB+63)/64, (NIMG+63)/64), 256>>>(h1p, wl2, xl2p, NIMG, 4*EMB, HIDD);
    sgemm_kernel<<<dim3((4*EMB+63)/64, (NIMG+63)/64), 256>>>(h1p, wr2, xr2p, NIMG, 4*EMB, HIDD);
    gat2_kernel<<<NIMG, 256>>>(att2, bias2, out + (size_t)NIMG*EMB);
}